// round 5
// baseline (speedup 1.0000x reference)
#include <cuda_runtime.h>
#include <cuda_bf16.h>
#include <cstdint>

// ---- model constants ----
constexpr int Bb = 32, Tt = 128, Dd = 128, Hh = 8, HDh = 16, Ll = 4;
constexpr int Vv = 50257;
constexpr int BT = Bb * Tt;           // 4096
constexpr int VP = 50304;             // V padded to multiple of 128

// ---- scratch (static device globals; no allocation allowed) ----
__device__ float g_h  [BT * Dd];                 // LNf output (fp32, for rownll)
__device__ float g_qkv[BT * 3 * Dd];
__device__ float g_nll[BT];                      // per-row nll scratch
__device__ float g_rowsum[BT];
__device__ __align__(16) __nv_bfloat16 g_lmwb[(size_t)VP * 256];   // lm head W: [n][hi128|lo128]
__device__ __align__(16) __nv_bfloat16 g_hb[(size_t)BT * 256];     // lm head A: [r][hi128|lo128]
// body weights, hi/lo bf16, B-operand layout [n][k-hi|k-lo]
__device__ __align__(16) __nv_bfloat16 g_wqkh[Ll * 384 * 256];
__device__ __align__(16) __nv_bfloat16 g_wprh[Ll * 128 * 256];
__device__ __align__(16) __nv_bfloat16 g_w1h [Ll * 512 * 256];
__device__ __align__(16) __nv_bfloat16 g_w2h [Ll * 128 * 4 * 256]; // [l][n][kc][256]
__device__ __align__(16) __nv_bfloat16 g_mlphl[Bb * 4 * 128 * 256]; // [b][kc][row][hi|lo]

__device__ __forceinline__ uint32_t smem_u32(const void* p) {
    uint32_t a;
    asm("{ .reg .u64 t; cvta.to.shared.u64 t, %1; cvt.u32.u64 %0, t; }" : "=r"(a) : "l"(p));
    return a;
}
__device__ __forceinline__ void f2hl(float v, __nv_bfloat16& hi, __nv_bfloat16& lo) {
    hi = __float2bfloat16(v);
    lo = __float2bfloat16(v - __bfloat162float(hi));
}

// ======================= weight conversion =======================
// y=0..2: wq/wk/wv -> g_wqkh ; y=3: wproj -> g_wprh ; y=4: w1 -> g_w1h ; y=5: w2 -> g_w2h
__global__ void wconv_kernel(const float* __restrict__ wq, const float* __restrict__ wk,
                             const float* __restrict__ wv, const float* __restrict__ wproj,
                             const float* __restrict__ w1, const float* __restrict__ w2) {
    int i = blockIdx.x * 256 + threadIdx.x;
    int m = blockIdx.y;
    if (m == 0 && i < BT) g_rowsum[i] = 0.f;
    if (m < 3) {
        if (i >= Ll * Hh * Dd * HDh) return;
        const float* src = (m == 0) ? wq : (m == 1) ? wk : wv;
        int e = i & 15, d = (i >> 4) & 127, h = (i >> 11) & 7, l = i >> 14;
        int n = m * 128 + h * 16 + e;
        float v = src[i];
        __nv_bfloat16 hi, lo; f2hl(v, hi, lo);
        size_t base = ((size_t)l * 384 + n) * 256;
        g_wqkh[base + d] = hi; g_wqkh[base + 128 + d] = lo;
    } else if (m == 3) {
        if (i >= Ll * Dd * Dd) return;
        int n = i & 127, d = (i >> 7) & 127, l = i >> 14;
        __nv_bfloat16 hi, lo; f2hl(wproj[i], hi, lo);
        size_t base = ((size_t)l * 128 + n) * 256;
        g_wprh[base + d] = hi; g_wprh[base + 128 + d] = lo;
    } else if (m == 4) {
        if (i >= Ll * Dd * 512) return;
        int n = i & 511, d = (i >> 9) & 127, l = i >> 16;
        __nv_bfloat16 hi, lo; f2hl(w1[i], hi, lo);
        size_t base = ((size_t)l * 512 + n) * 256;
        g_w1h[base + d] = hi; g_w1h[base + 128 + d] = lo;
    } else {
        if (i >= Ll * 512 * Dd) return;
        int n = i & 127, k = (i >> 7) & 511, l = i >> 16;
        int kc = k >> 7, ck = k & 127;
        __nv_bfloat16 hi, lo; f2hl(w2[i], hi, lo);
        size_t base = (((size_t)l * 128 + n) * 4 + kc) * 256;
        g_w2h[base + ck] = hi; g_w2h[base + 128 + ck] = lo;
    }
}

// lm_w [128][Vv] -> g_lmwb [VP][256] bf16 hi|lo (transposed, zero-padded)
__global__ void convw_kernel(const float* __restrict__ lm_w) {
    __shared__ float t[32][33];
    int nb = blockIdx.x * 32, kb = blockIdx.y * 32;
    int tx = threadIdx.x, ty = threadIdx.y;
    #pragma unroll
    for (int i = 0; i < 4; i++) {
        int k = kb + ty + 8 * i, n = nb + tx;
        t[ty + 8 * i][tx] = (n < Vv) ? lm_w[(size_t)k * Vv + n] : 0.f;
    }
    __syncthreads();
    #pragma unroll
    for (int i = 0; i < 4; i++) {
        int n = nb + ty + 8 * i, k = kb + tx;
        float v = t[tx][ty + 8 * i];
        __nv_bfloat16 hi, lo; f2hl(v, hi, lo);
        size_t base = (size_t)n * 256;
        g_lmwb[base + k] = hi; g_lmwb[base + 128 + k] = lo;
    }
}

// ======================= fused body =======================
constexpr int XB_S = 132;                         // fp32 row stride
constexpr int LMS = 264;                          // bf16 row stride (ldmatrix tiles)
constexpr int AHL_OFF = 128 * XB_S * 4;           // 67584
constexpr int BS_OFF  = AHL_OFF + 128 * LMS * 2;  // 135168
constexpr int AT_OFF  = BS_OFF;                   // attention scratch overlays BS
constexpr int BODY_SMEM = BS_OFF + 64 * LMS * 2;  // 168960

__device__ __forceinline__ void hmma_tile(const uint32_t a_base[2], const uint32_t b_base[4],
                                          float acc[2][4][4]) {
    #pragma unroll
    for (int p = 0; p < 3; p++) {
        int ka = (p == 1) ? 256 : 0;   // bytes: lo half of A
        int kb = (p == 2) ? 256 : 0;   // bytes: lo half of B
        #pragma unroll
        for (int ks = 0; ks < 8; ks++) {
            int ofA = ka + ks * 32;
            int ofB = kb + ks * 32;
            uint32_t a[2][4], b[4][2];
            #pragma unroll
            for (int i = 0; i < 2; i++)
                asm volatile("ldmatrix.sync.aligned.m8n8.x4.shared.b16 {%0,%1,%2,%3}, [%4];"
                             : "=r"(a[i][0]), "=r"(a[i][1]), "=r"(a[i][2]), "=r"(a[i][3])
                             : "r"(a_base[i] + ofA));
            #pragma unroll
            for (int j = 0; j < 4; j++)
                asm volatile("ldmatrix.sync.aligned.m8n8.x2.shared.b16 {%0,%1}, [%2];"
                             : "=r"(b[j][0]), "=r"(b[j][1])
                             : "r"(b_base[j] + ofB));
            #pragma unroll
            for (int i = 0; i < 2; i++)
                #pragma unroll
                for (int j = 0; j < 4; j++)
                    asm volatile(
                        "mma.sync.aligned.m16n8k16.row.col.f32.bf16.bf16.f32 "
                        "{%0,%1,%2,%3}, {%4,%5,%6,%7}, {%8,%9}, {%0,%1,%2,%3};"
                        : "+f"(acc[i][j][0]), "+f"(acc[i][j][1]),
                          "+f"(acc[i][j][2]), "+f"(acc[i][j][3])
                        : "r"(a[i][0]), "r"(a[i][1]), "r"(a[i][2]), "r"(a[i][3]),
                          "r"(b[j][0]), "r"(b[j][1]));
        }
    }
}

__device__ __forceinline__ void load_bs(char* smem, const __nv_bfloat16* __restrict__ src,
                                        int rowStride, int tid) {
    __nv_bfloat16* BS = (__nv_bfloat16*)(smem + BS_OFF);
    #pragma unroll
    for (int i = 0; i < 8; i++) {
        int idx = tid + i * 256;
        int r = idx >> 5, u = idx & 31;
        uint4 v = *(const uint4*)&src[(size_t)r * rowStride + u * 8];
        *(uint4*)&BS[r * LMS + u * 8] = v;
    }
}

// LN of XB rows -> AHL (bf16 hi/lo). One warp per row, 16 rows/warp.
__device__ __forceinline__ void ln_rows(char* smem, const float* __restrict__ g,
                                        const float* __restrict__ bp, int tid) {
    float* XB = (float*)smem;
    __nv_bfloat16* AHL = (__nv_bfloat16*)(smem + AHL_OFF);
    int w = tid >> 5, lane = tid & 31;
    for (int row = w; row < 128; row += 8) {
        float v[4], s = 0.f, s2 = 0.f;
        #pragma unroll
        for (int i = 0; i < 4; i++) {
            v[i] = XB[row * XB_S + lane + 32 * i];
            s += v[i]; s2 += v[i] * v[i];
        }
        #pragma unroll
        for (int o = 16; o; o >>= 1) {
            s  += __shfl_xor_sync(0xffffffffu, s,  o);
            s2 += __shfl_xor_sync(0xffffffffu, s2, o);
        }
        float mean = s * (1.f / 128.f);
        float var  = s2 * (1.f / 128.f) - mean * mean;
        float inv  = rsqrtf(var + 1e-5f);
        #pragma unroll
        for (int i = 0; i < 4; i++) {
            int d = lane + 32 * i;
            float o = (v[i] - mean) * inv * g[d] + bp[d];
            __nv_bfloat16 hi, lo; f2hl(o, hi, lo);
            AHL[row * LMS + d] = hi;
            AHL[row * LMS + 128 + d] = lo;
        }
    }
}

// attention for sample b: reads g_qkv, writes o as hi/lo into AHL
__device__ __forceinline__ void attn_block(char* smem, int b, int tid) {
    float* k_s = (float*)(smem + AT_OFF);        // [16][129]
    float* v_s = k_s + 16 * 129;                 // [16][129]
    float* p_s = v_s + 16 * 129;                 // [8][128]
    __nv_bfloat16* AHL = (__nv_bfloat16*)(smem + AHL_OFF);
    int w = tid >> 5, lane = tid & 31;
    int base_bt = b * Tt;
    const float scale = 0.08838834764831845f;    // D^-0.5
    for (int h = 0; h < 8; h++) {
        __syncthreads();
        for (int i = tid; i < Tt * HDh; i += 256) {
            int s = i >> 4, e = i & 15;
            size_t g = (size_t)(base_bt + s) * 384 + h * HDh + e;
            k_s[e * 129 + s] = g_qkv[g + 128];
            v_s[e * 129 + s] = g_qkv[g + 256];
        }
        __syncthreads();
        for (int t = w; t < Tt; t += 8) {
            float q[16];
            size_t qg = (size_t)(base_bt + t) * 384 + h * HDh;
            #pragma unroll
            for (int e = 0; e < 16; e++) q[e] = g_qkv[qg + e];
            float sc[4];
            #pragma unroll
            for (int j = 0; j < 4; j++) {
                int s = lane + 32 * j;
                float dot = 0.f;
                #pragma unroll
                for (int e = 0; e < 16; e++) dot += q[e] * k_s[e * 129 + s];
                sc[j] = (s <= t) ? dot * scale : -1e30f;
            }
            float m = fmaxf(fmaxf(sc[0], sc[1]), fmaxf(sc[2], sc[3]));
            #pragma unroll
            for (int o = 16; o; o >>= 1) m = fmaxf(m, __shfl_xor_sync(0xffffffffu, m, o));
            float p[4], ps = 0.f;
            #pragma unroll
            for (int j = 0; j < 4; j++) {
                int s = lane + 32 * j;
                p[j] = (s <= t) ? __expf(sc[j] - m) : 0.f;
                ps += p[j];
            }
            #pragma unroll
            for (int o = 16; o; o >>= 1) ps += __shfl_xor_sync(0xffffffffu, ps, o);
            float inv = 1.f / ps;
            #pragma unroll
            for (int j = 0; j < 4; j++) p_s[w * 128 + lane + 32 * j] = p[j] * inv;
            __syncwarp();
            int e = lane & 15, half = lane >> 4;
            float acc = 0.f;
            int sb = half * 64;
            #pragma unroll
            for (int s = 0; s < 64; s++) acc += p_s[w * 128 + sb + s] * v_s[e * 129 + sb + s];
            acc += __shfl_xor_sync(0xffffffffu, acc, 16);
            if (lane < 16) {
                __nv_bfloat16 hi, lo; f2hl(acc, hi, lo);
                AHL[t * LMS + h * 16 + e] = hi;
                AHL[t * LMS + 128 + h * 16 + e] = lo;
            }
            __syncwarp();
        }
    }
}

__global__ __launch_bounds__(256, 1)
void body_kernel(const int* __restrict__ idx,
                 const float* __restrict__ tok, const float* __restrict__ pos,
                 const float* __restrict__ bproj, const float* __restrict__ b1,
                 const float* __restrict__ b2,
                 const float* __restrict__ ln1g, const float* __restrict__ ln1b,
                 const float* __restrict__ ln2g, const float* __restrict__ ln2b,
                 const float* __restrict__ lnfg, const float* __restrict__ lnfb) {
    extern __shared__ char smem[];
    float* XB = (float*)smem;
    int b = blockIdx.x, tid = threadIdx.x;
    int wid = tid >> 5, lane = tid & 31;
    int wm = (wid & 3) * 32, wn = (wid >> 2) * 32;

    // embed
    for (int i = tid; i < 128 * 128; i += 256) {
        int row = i >> 7, d = i & 127;
        XB[row * XB_S + d] = tok[(size_t)idx[b * 128 + row] * 128 + d] + pos[row * 128 + d];
    }

    // ldmatrix base addresses (fixed per thread)
    uint32_t a_base[2], b_base[4];
    {
        __nv_bfloat16* AHL = (__nv_bfloat16*)(smem + AHL_OFF);
        __nv_bfloat16* BS  = (__nv_bfloat16*)(smem + BS_OFF);
        #pragma unroll
        for (int i = 0; i < 2; i++) {
            int row = wm + i * 16 + (lane & 15);
            int col = (lane >> 4) * 8;
            a_base[i] = smem_u32(&AHL[row * LMS + col]);
        }
        #pragma unroll
        for (int j = 0; j < 4; j++) {
            int row = wn + j * 8 + (lane & 7);
            int col = ((lane >> 3) & 1) * 8;
            b_base[j] = smem_u32(&BS[row * LMS + col]);
        }
    }
    __syncthreads();

    for (int l = 0; l < Ll; l++) {
        // ---- LN1 -> AHL ----
        ln_rows(smem, ln1g + l * 128, ln1b + l * 128, tid);
        __syncthreads();
        // ---- qkv: 6 chunks of 64 cols -> g_qkv ----
        for (int c = 0; c < 6; c++) {
            __syncthreads();
            load_bs(smem, g_wqkh + ((size_t)l * 384 + c * 64) * 256, 256, tid);
            __syncthreads();
            float acc[2][4][4] = {};
            hmma_tile(a_base, b_base, acc);
            #pragma unroll
            for (int i = 0; i < 2; i++)
                #pragma unroll
                for (int hf = 0; hf < 2; hf++) {
                    int row = wm + i * 16 + (lane >> 2) + hf * 8;
                    #pragma unroll
                    for (int j = 0; j < 4; j++) {
                        int gc = c * 64 + wn + j * 8 + (lane & 3) * 2;
                        size_t o = (size_t)(b * 128 + row) * 384 + gc;
                        g_qkv[o]     = acc[i][j][hf * 2];
                        g_qkv[o + 1] = acc[i][j][hf * 2 + 1];
                    }
                }
        }
        __syncthreads();
        // ---- attention -> AHL ----
        attn_block(smem, b, tid);
        __syncthreads();
        // ---- proj: 2 chunks, XB += o@wproj + bproj ----
        for (int c = 0; c < 2; c++) {
            __syncthreads();
            load_bs(smem, g_wprh + ((size_t)l * 128 + c * 64) * 256, 256, tid);
            __syncthreads();
            float acc[2][4][4] = {};
            hmma_tile(a_base, b_base, acc);
            #pragma unroll
            for (int i = 0; i < 2; i++)
                #pragma unroll
                for (int hf = 0; hf < 2; hf++) {
                    int row = wm + i * 16 + (lane >> 2) + hf * 8;
                    #pragma unroll
                    for (int j = 0; j < 4; j++) {
                        int gc = c * 64 + wn + j * 8 + (lane & 3) * 2;
                        XB[row * XB_S + gc]     += acc[i][j][hf * 2]     + bproj[l * 128 + gc];
                        XB[row * XB_S + gc + 1] += acc[i][j][hf * 2 + 1] + bproj[l * 128 + gc + 1];
                    }
                }
        }
        __syncthreads();
        // ---- LN2 -> AHL ----
        ln_rows(smem, ln2g + l * 128, ln2b + l * 128, tid);
        __syncthreads();
        // ---- mlp1: 8 chunks -> relu -> g_mlphl (hi/lo) ----
        for (int c = 0; c < 8; c++) {
            __syncthreads();
            load_bs(smem, g_w1h + ((size_t)l * 512 + c * 64) * 256, 256, tid);
            __syncthreads();
            float acc[2][4][4] = {};
            hmma_tile(a_base, b_base, acc);
            #pragma unroll
            for (int i = 0; i < 2; i++)
                #pragma unroll
                for (int hf = 0; hf < 2; hf++) {
                    int row = wm + i * 16 + (lane >> 2) + hf * 8;
                    #pragma unroll
                    for (int j = 0; j < 4; j++) {
                        int gc = c * 64 + wn + j * 8 + (lane & 3) * 2;
                        #pragma unroll
                        for (int q = 0; q < 2; q++) {
                            int gcq = gc + q;
                            float v = fmaxf(acc[i][j][hf * 2 + q] + b1[l * 512 + gcq], 0.f);
                            __nv_bfloat16 hi, lo; f2hl(v, hi, lo);
                            int kc = gcq >> 7, ck = gcq & 127;
                            size_t dst = (((size_t)(b * 4 + kc)) * 128 + row) * 256 + ck;
                            g_mlphl[dst]       = hi;
                            g_mlphl[dst + 128] = lo;
                        }
                    }
                }
        }
        // ---- mlp2: K=512 over 4 k-chunks, N=128 over 2 n-chunks ----
        float acc2[2][2][4][4];
        #pragma unroll
        for (int nc = 0; nc < 2; nc++)
            #pragma unroll
            for (int i = 0; i < 2; i++)
                #pragma unroll
                for (int j = 0; j < 4; j++)
                    #pragma unroll
                    for (int q = 0; q < 4; q++) acc2[nc][i][j][q] = 0.f;
        for (int kc = 0; kc < 4; kc++) {
            __syncthreads();
            // load AHL <- g_mlphl[b][kc]
            {
                __nv_bfloat16* AHL = (__nv_bfloat16*)(smem + AHL_OFF);
                #pragma unroll
                for (int i2 = 0; i2 < 16; i2++) {
                    int idx2 = tid + i2 * 256;
                    int r = idx2 >> 5, u = idx2 & 31;
                    uint4 v = *(const uint4*)&g_mlphl[(((size_t)(b * 4 + kc)) * 128 + r) * 256 + u * 8];
                    *(uint4*)&AHL[r * LMS + u * 8] = v;
                }
            }
            __syncthreads();
            for (int nc = 0; nc < 2; nc++) {
                load_bs(smem, g_w2h + (((size_t)l * 128 + nc * 64) * 4 + kc) * 256, 1024, tid);
                __syncthreads();
                hmma_tile(a_base, b_base, acc2[nc]);
                __syncthreads();
            }
        }
        #pragma unroll
        for (int nc = 0; nc < 2; nc++)
            #pragma unroll
            for (int i = 0; i < 2; i++)
                #pragma unroll
                for (int hf = 0; hf < 2; hf++) {
                    int row = wm + i * 16 + (lane >> 2) + hf * 8;
                    #pragma unroll
                    for (int j = 0; j < 4; j++) {
                        int gc = nc * 64 + wn + j * 8 + (lane & 3) * 2;
                        XB[row * XB_S + gc]     += acc2[nc][i][j][hf * 2]     + b2[l * 128 + gc];
                        XB[row * XB_S + gc + 1] += acc2[nc][i][j][hf * 2 + 1] + b2[l * 128 + gc + 1];
                    }
                }
        __syncthreads();
    }

    // ---- final LN -> g_h (fp32) + g_hb (hi/lo) ----
    {
        int w = tid >> 5, ln = tid & 31;
        for (int row = w; row < 128; row += 8) {
            float v[4], s = 0.f, s2 = 0.f;
            #pragma unroll
            for (int i = 0; i < 4; i++) {
                v[i] = XB[row * XB_S + ln + 32 * i];
                s += v[i]; s2 += v[i] * v[i];
            }
            #pragma unroll
            for (int o = 16; o; o >>= 1) {
                s  += __shfl_xor_sync(0xffffffffu, s,  o);
                s2 += __shfl_xor_sync(0xffffffffu, s2, o);
            }
            float mean = s * (1.f / 128.f);
            float var  = s2 * (1.f / 128.f) - mean * mean;
            float inv  = rsqrtf(var + 1e-5f);
            #pragma unroll
            for (int i = 0; i < 4; i++) {
                int d = ln + 32 * i;
                float o = (v[i] - mean) * inv * lnfg[d] + lnfb[d];
                g_h[(size_t)(b * 128 + row) * 128 + d] = o;
                __nv_bfloat16 hi, lo; f2hl(o, hi, lo);
                g_hb[(size_t)(b * 128 + row) * 256 + d] = hi;
                g_hb[(size_t)(b * 128 + row) * 256 + 128 + d] = lo;
            }
        }
    }
}

// ======================= LM head (HMMA, unchanged from round 4) =======================
__global__ __launch_bounds__(256, 2)
void lmhead_hmma(const float* __restrict__ lmb, float* __restrict__ out) {
    extern __shared__ __nv_bfloat16 sm[];
    __nv_bfloat16* As = sm;               // 128 x LMS
    __nv_bfloat16* Bs = sm + 128 * LMS;   // 64 x LMS
    int tid = threadIdx.x;
    int m0 = blockIdx.x * 128, n0 = blockIdx.y * 64;

    #pragma unroll
    for (int i = 0; i < 16; i++) {
        int idx = tid + i * 256;
        int r = idx >> 5, u = idx & 31;
        uint4 v = *(const uint4*)&g_hb[((size_t)(m0 + r)) * 256 + u * 8];
        *(uint4*)&As[r * LMS + u * 8] = v;
    }
    #pragma unroll
    for (int i = 0; i < 8; i++) {
        int idx = tid + i * 256;
        int r = idx >> 5, u = idx & 31;
        uint4 v = *(const uint4*)&g_lmwb[((size_t)(n0 + r)) * 256 + u * 8];
        *(uint4*)&Bs[r * LMS + u * 8] = v;
    }
    __syncthreads();

    int wid = tid >> 5, lane = tid & 31;
    int wm = (wid & 3) * 32;
    int wn = (wid >> 2) * 32;

    uint32_t a_base[2], b_base[4];
    #pragma unroll
    for (int i = 0; i < 2; i++) {
        int row = wm + i * 16 + (lane & 15);
        int col = (lane >> 4) * 8;
        a_base[i] = smem_u32(&As[row * LMS + col]);
    }
    #pragma unroll
    for (int j = 0; j < 4; j++) {
        int row = wn + j * 8 + (lane & 7);
        int col = ((lane >> 3) & 1) * 8;
        b_base[j] = smem_u32(&Bs[row * LMS + col]);
    }

    float acc[2][4][4] = {};
    hmma_tile(a_base, b_base, acc);

    float bias0[4], bias1[4];
    #pragma unroll
    for (int j = 0; j < 4; j++) {
        int c = n0 + wn + j * 8 + (lane & 3) * 2;
        bias0[j] = (c < Vv) ? lmb[c] : 0.f;
        bias1[j] = (c + 1 < Vv) ? lmb[c + 1] : 0.f;
    }

    #pragma unroll
    for (int i = 0; i < 2; i++) {
        #pragma unroll
        for (int hf = 0; hf < 2; hf++) {
            int row = m0 + wm + i * 16 + (lane >> 2) + hf * 8;
            size_t ro = (size_t)row * Vv;
            float rexp = 0.f;
            #pragma unroll
            for (int j = 0; j < 4; j++) {
                int c = n0 + wn + j * 8 + (lane & 3) * 2;
                float v0 = acc[i][j][hf * 2]     + bias0[j];
                float v1 = acc[i][j][hf * 2 + 1] + bias1[j];
                if (c < Vv) {
                    if (out) out[ro + c] = v0;
                    rexp += __expf(v0);
                }
                if (c + 1 < Vv) {
                    if (out) out[ro + c + 1] = v1;
                    rexp += __expf(v1);
                }
            }
            rexp += __shfl_xor_sync(0xffffffffu, rexp, 1);
            rexp += __shfl_xor_sync(0xffffffffu, rexp, 2);
            if ((lane & 3) == 0) atomicAdd(&g_rowsum[row], rexp);
        }
    }
}

// ======================= loss =======================
__global__ void rownll_kernel(const int* __restrict__ targets,
                              const float* __restrict__ lm_w,
                              const float* __restrict__ lmb) {
    int gw = (blockIdx.x * blockDim.x + threadIdx.x) >> 5;
    int lane = threadIdx.x & 31;
    for (int r = gw; r < BT; r += 512) {
        int tgt = targets[r];
        float dot = 0.f;
        const float* xr = &g_h[(size_t)r * Dd];
        #pragma unroll
        for (int i = 0; i < 4; i++) {
            int d = lane + 32 * i;
            dot += xr[d] * lm_w[(size_t)d * Vv + tgt];
        }
        #pragma unroll
        for (int o = 16; o; o >>= 1) dot += __shfl_xor_sync(0xffffffffu, dot, o);
        if (lane == 0) g_nll[r] = logf(g_rowsum[r]) - (dot + lmb[tgt]);
    }
}

__global__ void lossred_kernel(float* __restrict__ loss_out) {
    int tid = threadIdx.x;
    float local = 0.f;
    for (int r = tid; r < BT; r += 1024) local += g_nll[r];
    #pragma unroll
    for (int o = 16; o; o >>= 1) local += __shfl_xor_sync(0xffffffffu, local, o);
    __shared__ float red[32];
    if ((tid & 31) == 0) red[tid >> 5] = local;
    __syncthreads();
    if (tid < 32) {
        float v = red[tid];
        #pragma unroll
        for (int o = 16; o; o >>= 1) v += __shfl_xor_sync(0xffffffffu, v, o);
        if (tid == 0 && loss_out) *loss_out = v * (1.f / (float)BT);
    }
}

// ======================= launch =======================
extern "C" void kernel_launch(void* const* d_in, const int* in_sizes, int n_in,
                              void* d_out, int out_size) {
    const int*   idx     = (const int*)  d_in[0];
    const int*   targets = (const int*)  d_in[1];
    const float* tok_emb = (const float*)d_in[2];
    const float* pos_emb = (const float*)d_in[3];
    const float* wq      = (const float*)d_in[4];
    const float* wk      = (const float*)d_in[5];
    const float* wv      = (const float*)d_in[6];
    const float* wproj   = (const float*)d_in[7];
    const float* bproj   = (const float*)d_in[8];
    const float* w1      = (const float*)d_in[9];
    const float* b1      = (const float*)d_in[10];
    const float* w2      = (const float*)d_in[11];
    const float* b2      = (const float*)d_in[12];
    const float* ln1_g   = (const float*)d_in[13];
    const float* ln1_b   = (const float*)d_in[14];
    const float* ln2_g   = (const float*)d_in[15];
    const float* ln2_b   = (const float*)d_in[16];
    const float* lnf_g   = (const float*)d_in[17];
    const float* lnf_b   = (const float*)d_in[18];
    const float* lm_w    = (const float*)d_in[19];
    const float* lm_b    = (const float*)d_in[20];

    float* outf = (float*)d_out;
    long long btv = (long long)BT * Vv;
    float* logits = ((long long)out_size >= btv) ? outf : nullptr;
    float* lossp  = nullptr;
    if ((long long)out_size == btv + 1) lossp = outf + btv;
    else if ((long long)out_size < btv && out_size >= 1) lossp = outf + (out_size - 1);

    constexpr int LM_SMEM = (128 * LMS + 64 * LMS) * 2;  // 101376
    cudaFuncSetAttribute(lmhead_hmma, cudaFuncAttributeMaxDynamicSharedMemorySize, LM_SMEM);
    cudaFuncSetAttribute(body_kernel, cudaFuncAttributeMaxDynamicSharedMemorySize, BODY_SMEM);

    wconv_kernel<<<dim3(1024, 6), 256>>>(wq, wk, wv, wproj, w1, w2);
    convw_kernel<<<dim3(VP / 32, 4), dim3(32, 8)>>>(lm_w);
    body_kernel<<<Bb, 256, BODY_SMEM>>>(idx, tok_emb, pos_emb, bproj, b1, b2,
                                        ln1_g, ln1_b, ln2_g, ln2_b, lnf_g, lnf_b);
    lmhead_hmma<<<dim3(BT / 128, VP / 64), 256, LM_SMEM>>>(lm_b, logits);
    rownll_kernel<<<64, 256>>>(targets, lm_w, lm_b);
    lossred_kernel<<<1, 1024>>>(lossp);
}

// round 6
// speedup vs baseline: 1.2017x; 1.2017x over previous
#include <cuda_runtime.h>
#include <cuda_bf16.h>
#include <cuda_fp16.h>
#include <cstdint>

// ---- model constants ----
constexpr int Bb = 32, Tt = 128, Dd = 128, Hh = 8, HDh = 16, Ll = 4;
constexpr int Vv = 50257;
constexpr int BT = Bb * Tt;           // 4096
constexpr int VP = 50304;             // V padded to multiple of 128

// ---- scratch (static device globals; no allocation allowed) ----
__device__ float g_x  [BT * Dd];
__device__ float g_h  [BT * Dd];
__device__ float g_qkv[BT * 3 * Dd];
__device__ float g_att[BT * Dd];      // reused as per-row nll scratch at the end
__device__ float g_mlp[BT * 4 * Dd];
__device__ float g_wqkv[Ll * Dd * 3 * Dd];
__device__ float g_rowsum[BT];
__device__ __align__(16) __nv_bfloat16 g_lmwb[(size_t)VP * 256];  // [n][0:128]=hi,[128:256]=lo
__device__ __align__(16) __nv_bfloat16 g_hb[(size_t)BT * 256];    // [r][0:128]=hi,[128:256]=lo

__device__ __forceinline__ float* buf_sel(int s) {
    switch (s) {
        case 0: return g_x;
        case 1: return g_h;
        case 2: return g_qkv;
        case 3: return g_att;
        default: return g_mlp;
    }
}

__device__ __forceinline__ uint32_t smem_u32(const void* p) {
    uint32_t a;
    asm("{ .reg .u64 t; cvta.to.shared.u64 t, %1; cvt.u32.u64 %0, t; }" : "=r"(a) : "l"(p));
    return a;
}

// ======================= small prep kernels =======================
__global__ void prep_kernel(const float* __restrict__ wq,
                            const float* __restrict__ wk,
                            const float* __restrict__ wv) {
    int i = blockIdx.x * blockDim.x + threadIdx.x;
    if (i < BT) g_rowsum[i] = 0.f;
    if (i < Ll * Hh * Dd * HDh) {
        int e = i & 15;
        int d = (i >> 4) & 127;
        int h = (i >> 11) & 7;
        int l = i >> 14;
        int dst = (l * Dd + d) * 384 + h * HDh + e;
        g_wqkv[dst]       = wq[i];
        g_wqkv[dst + 128] = wk[i];
        g_wqkv[dst + 256] = wv[i];
    }
}

// lm_w [128][Vv] -> g_lmwb [VP][256] bf16 hi|lo (transposed, zero-padded)
__global__ void convw_kernel(const float* __restrict__ lm_w) {
    __shared__ float t[32][33];
    int nb = blockIdx.x * 32, kb = blockIdx.y * 32;
    int tx = threadIdx.x, ty = threadIdx.y;
    #pragma unroll
    for (int i = 0; i < 4; i++) {
        int k = kb + ty + 8 * i, n = nb + tx;
        t[ty + 8 * i][tx] = (n < Vv) ? lm_w[(size_t)k * Vv + n] : 0.f;
    }
    __syncthreads();
    #pragma unroll
    for (int i = 0; i < 4; i++) {
        int n = nb + ty + 8 * i, k = kb + tx;
        float v = t[tx][ty + 8 * i];
        __nv_bfloat16 hi = __float2bfloat16(v);
        __nv_bfloat16 lo = __float2bfloat16(v - __bfloat162float(hi));
        size_t base = (size_t)n * 256;
        g_lmwb[base + k]       = hi;
        g_lmwb[base + 128 + k] = lo;
    }
}

// g_h [BT][128] -> g_hb [BT][256] bf16 hi|lo
__global__ void convh_kernel() {
    int i = blockIdx.x * 256 + threadIdx.x;
    if (i >= BT * Dd) return;
    int r = i >> 7, k = i & 127;
    float v = g_h[i];
    __nv_bfloat16 hi = __float2bfloat16(v);
    __nv_bfloat16 lo = __float2bfloat16(v - __bfloat162float(hi));
    g_hb[(size_t)r * 256 + k]       = hi;
    g_hb[(size_t)r * 256 + 128 + k] = lo;
}

__global__ void embed_kernel(const int* __restrict__ idx,
                             const float* __restrict__ tok,
                             const float* __restrict__ pos) {
    int bt = blockIdx.x, d = threadIdx.x;
    int t = bt & (Tt - 1);
    g_x[bt * Dd + d] = tok[(size_t)idx[bt] * Dd + d] + pos[t * Dd + d];
}

__global__ void ln_kernel(const float* __restrict__ g, const float* __restrict__ b) {
    int row = blockIdx.x, tid = threadIdx.x;
    float v = g_x[row * Dd + tid];
    float s = v, s2 = v * v;
    #pragma unroll
    for (int o = 16; o; o >>= 1) {
        s  += __shfl_xor_sync(0xffffffffu, s,  o);
        s2 += __shfl_xor_sync(0xffffffffu, s2, o);
    }
    __shared__ float sh[8];
    int w = tid >> 5;
    if ((tid & 31) == 0) { sh[w] = s; sh[4 + w] = s2; }
    __syncthreads();
    float ts  = sh[0] + sh[1] + sh[2] + sh[3];
    float ts2 = sh[4] + sh[5] + sh[6] + sh[7];
    float mean = ts * (1.f / 128.f);
    float var  = ts2 * (1.f / 128.f) - mean * mean;
    g_h[row * Dd + tid] = (v - mean) * rsqrtf(var + 1e-5f) * g[tid] + b[tid];
}

// ======================= body GEMM =======================
__global__ __launch_bounds__(256)
void gemm64_kernel(int asel, const float* __restrict__ Bext, int bofs,
                   const float* __restrict__ bias, int use_res, int csel,
                   int N, int K, int relu) {
    __shared__ float As[32][65];
    __shared__ __align__(16) float Bs[32][64];
    const float* A = buf_sel(asel);
    float* C = buf_sel(csel);
    const float* Bm = Bext ? Bext : (g_wqkv + bofs);
    int tid = threadIdx.x;
    int tx = tid & 15, ty = tid >> 4;
    int r0 = blockIdx.y * 64, c0 = blockIdx.x * 64;
    int ar = tid >> 3, ak = (tid & 7) * 4;
    int br = tid >> 4, bc = (tid & 15) * 4;
    float acc[4][4] = {};
    for (int k0 = 0; k0 < K; k0 += 32) {
        float4 a0 = *(const float4*)&A[(size_t)(r0 + ar)      * K + k0 + ak];
        float4 a1 = *(const float4*)&A[(size_t)(r0 + ar + 32) * K + k0 + ak];
        As[ak + 0][ar] = a0.x; As[ak + 1][ar] = a0.y;
        As[ak + 2][ar] = a0.z; As[ak + 3][ar] = a0.w;
        As[ak + 0][ar + 32] = a1.x; As[ak + 1][ar + 32] = a1.y;
        As[ak + 2][ar + 32] = a1.z; As[ak + 3][ar + 32] = a1.w;
        *(float4*)&Bs[br][bc]      = *(const float4*)&Bm[(size_t)(k0 + br)      * N + c0 + bc];
        *(float4*)&Bs[br + 16][bc] = *(const float4*)&Bm[(size_t)(k0 + br + 16) * N + c0 + bc];
        __syncthreads();
        #pragma unroll
        for (int kk = 0; kk < 32; kk++) {
            float4 bv = *(const float4*)&Bs[kk][tx * 4];
            float a0r = As[kk][ty * 4 + 0];
            float a1r = As[kk][ty * 4 + 1];
            float a2r = As[kk][ty * 4 + 2];
            float a3r = As[kk][ty * 4 + 3];
            acc[0][0] += a0r * bv.x; acc[0][1] += a0r * bv.y; acc[0][2] += a0r * bv.z; acc[0][3] += a0r * bv.w;
            acc[1][0] += a1r * bv.x; acc[1][1] += a1r * bv.y; acc[1][2] += a1r * bv.z; acc[1][3] += a1r * bv.w;
            acc[2][0] += a2r * bv.x; acc[2][1] += a2r * bv.y; acc[2][2] += a2r * bv.z; acc[2][3] += a2r * bv.w;
            acc[3][0] += a3r * bv.x; acc[3][1] += a3r * bv.y; acc[3][2] += a3r * bv.z; acc[3][3] += a3r * bv.w;
        }
        __syncthreads();
    }
    #pragma unroll
    for (int i = 0; i < 4; i++) {
        int rr = r0 + ty * 4 + i;
        #pragma unroll
        for (int j = 0; j < 4; j++) {
            int cc = c0 + tx * 4 + j;
            float v = acc[i][j];
            if (bias) v += bias[cc];
            if (relu) v = fmaxf(v, 0.f);
            if (use_res) v += g_x[(size_t)rr * N + cc];
            C[(size_t)rr * N + cc] = v;
        }
    }
}

// ======================= attention =======================
__global__ void attn_kernel() {
    __shared__ float k_s[16][129];
    __shared__ float v_s[16][129];
    __shared__ float p_s[4][128];
    int bh = blockIdx.x;
    int b = bh >> 3, h = bh & 7;
    int tid = threadIdx.x;
    int w = tid >> 5, lane = tid & 31;
    int base_bt = b * Tt;
    for (int i = tid; i < Tt * HDh; i += 128) {
        int s = i >> 4, e = i & 15;
        size_t g = (size_t)(base_bt + s) * 384 + h * HDh + e;
        k_s[e][s] = g_qkv[g + 128];
        v_s[e][s] = g_qkv[g + 256];
    }
    __syncthreads();
    const float scale = 0.08838834764831845f;
    for (int t = w; t < Tt; t += 4) {
        float q[16];
        size_t qg = (size_t)(base_bt + t) * 384 + h * HDh;
        #pragma unroll
        for (int e = 0; e < 16; e++) q[e] = g_qkv[qg + e];
        float sc[4];
        #pragma unroll
        for (int j = 0; j < 4; j++) {
            int s = lane + 32 * j;
            float dot = 0.f;
            #pragma unroll
            for (int e = 0; e < 16; e++) dot += q[e] * k_s[e][s];
            sc[j] = (s <= t) ? dot * scale : -1e30f;
        }
        float m = fmaxf(fmaxf(sc[0], sc[1]), fmaxf(sc[2], sc[3]));
        #pragma unroll
        for (int o = 16; o; o >>= 1) m = fmaxf(m, __shfl_xor_sync(0xffffffffu, m, o));
        float p[4], ps = 0.f;
        #pragma unroll
        for (int j = 0; j < 4; j++) {
            int s = lane + 32 * j;
            p[j] = (s <= t) ? __expf(sc[j] - m) : 0.f;
            ps += p[j];
        }
        #pragma unroll
        for (int o = 16; o; o >>= 1) ps += __shfl_xor_sync(0xffffffffu, ps, o);
        float inv = 1.f / ps;
        #pragma unroll
        for (int j = 0; j < 4; j++) p_s[w][lane + 32 * j] = p[j] * inv;
        __syncwarp();
        int e = lane & 15, half = lane >> 4;
        float acc = 0.f;
        int sb = half * 64;
        #pragma unroll
        for (int s = 0; s < 64; s++) acc += p_s[w][sb + s] * v_s[e][sb + s];
        acc += __shfl_xor_sync(0xffffffffu, acc, 16);
        if (lane < 16) g_att[(size_t)(base_bt + t) * Dd + h * HDh + e] = acc;
        __syncwarp();
    }
}

// ======================= LM head (HMMA bf16 hi/lo; f16x2 exp epilogue) =======================
// Block tile: 128(M) x 64(N). 8 warps = 4(m) x 2(n), warp tile 32x32.
constexpr int LMS = 264;  // row stride in bf16 elems

__global__ __launch_bounds__(256, 2)
void lmhead_hmma(const float* __restrict__ lmb, float* __restrict__ out) {
    extern __shared__ __nv_bfloat16 sm[];
    __nv_bfloat16* As = sm;               // 128 x LMS
    __nv_bfloat16* Bs = sm + 128 * LMS;   // 64 x LMS
    int tid = threadIdx.x;
    int m0 = blockIdx.x * 128, n0 = blockIdx.y * 64;

    #pragma unroll
    for (int i = 0; i < 16; i++) {
        int idx = tid + i * 256;
        int r = idx >> 5, u = idx & 31;
        uint4 v = *(const uint4*)&g_hb[((size_t)(m0 + r)) * 256 + u * 8];
        *(uint4*)&As[r * LMS + u * 8] = v;
    }
    #pragma unroll
    for (int i = 0; i < 8; i++) {
        int idx = tid + i * 256;
        int r = idx >> 5, u = idx & 31;
        uint4 v = *(const uint4*)&g_lmwb[((size_t)(n0 + r)) * 256 + u * 8];
        *(uint4*)&Bs[r * LMS + u * 8] = v;
    }
    __syncthreads();

    int wid = tid >> 5, lane = tid & 31;
    int wm = (wid & 3) * 32;     // warp m offset
    int wn = (wid >> 2) * 32;    // warp n offset

    // A ldmatrix x4 bases (2 x m16 frags)
    uint32_t a_base[2];
    #pragma unroll
    for (int i = 0; i < 2; i++) {
        int row = wm + i * 16 + (lane & 15);
        int col = (lane >> 4) * 8;
        a_base[i] = smem_u32(&As[row * LMS + col]);
    }
    // B ldmatrix x4 bases: each x4 load yields frags for two n8 tiles (j=2jj, 2jj+1)
    uint32_t b_base4[2];
    #pragma unroll
    for (int jj = 0; jj < 2; jj++) {
        int row = wn + jj * 16 + ((lane >> 4) & 1) * 8 + (lane & 7);
        int col = ((lane >> 3) & 1) * 8;
        b_base4[jj] = smem_u32(&Bs[row * LMS + col]);
    }

    float acc[2][4][4];
    #pragma unroll
    for (int i = 0; i < 2; i++)
        #pragma unroll
        for (int j = 0; j < 4; j++)
            #pragma unroll
            for (int q = 0; q < 4; q++) acc[i][j][q] = 0.f;

    // 3 products: (Ah,Bh) (Al,Bh) (Ah,Bl); k-offsets in BYTES (128 elems = 256B)
    #pragma unroll
    for (int p = 0; p < 3; p++) {
        int ka = (p == 1) ? 256 : 0;
        int kb = (p == 2) ? 256 : 0;
        #pragma unroll
        for (int ks = 0; ks < 8; ks++) {
            int ofA = ka + ks * 32;
            int ofB = kb + ks * 32;
            uint32_t a[2][4], b[4][2];
            #pragma unroll
            for (int i = 0; i < 2; i++)
                asm volatile("ldmatrix.sync.aligned.m8n8.x4.shared.b16 {%0,%1,%2,%3}, [%4];"
                             : "=r"(a[i][0]), "=r"(a[i][1]), "=r"(a[i][2]), "=r"(a[i][3])
                             : "r"(a_base[i] + ofA));
            #pragma unroll
            for (int jj = 0; jj < 2; jj++)
                asm volatile("ldmatrix.sync.aligned.m8n8.x4.shared.b16 {%0,%1,%2,%3}, [%4];"
                             : "=r"(b[2 * jj][0]), "=r"(b[2 * jj][1]),
                               "=r"(b[2 * jj + 1][0]), "=r"(b[2 * jj + 1][1])
                             : "r"(b_base4[jj] + ofB));
            #pragma unroll
            for (int i = 0; i < 2; i++)
                #pragma unroll
                for (int j = 0; j < 4; j++)
                    asm volatile(
                        "mma.sync.aligned.m16n8k16.row.col.f32.bf16.bf16.f32 "
                        "{%0,%1,%2,%3}, {%4,%5,%6,%7}, {%8,%9}, {%0,%1,%2,%3};"
                        : "+f"(acc[i][j][0]), "+f"(acc[i][j][1]),
                          "+f"(acc[i][j][2]), "+f"(acc[i][j][3])
                        : "r"(a[i][0]), "r"(a[i][1]), "r"(a[i][2]), "r"(a[i][3]),
                          "r"(b[j][0]), "r"(b[j][1]));
        }
    }

    // bias (cols fixed per thread)
    float bias0[4], bias1[4];
    #pragma unroll
    for (int j = 0; j < 4; j++) {
        int c = n0 + wn + j * 8 + (lane & 3) * 2;
        bias0[j] = (c < Vv) ? lmb[c] : 0.f;
        bias1[j] = (c + 1 < Vv) ? lmb[c + 1] : 0.f;
    }

    const __half2 l2e2 = __float2half2_rn(1.4426950408889634f);

    // epilogue: bias, coalesced logits store, row sum(exp) via ex2.approx.f16x2
    #pragma unroll
    for (int i = 0; i < 2; i++) {
        #pragma unroll
        for (int hf = 0; hf < 2; hf++) {
            int row = m0 + wm + i * 16 + (lane >> 2) + hf * 8;
            size_t ro = (size_t)row * Vv;
            __half2 hs = __float2half2_rn(0.f);
            #pragma unroll
            for (int j = 0; j < 4; j++) {
                int c = n0 + wn + j * 8 + (lane & 3) * 2;
                float v0 = acc[i][j][hf * 2]     + bias0[j];
                float v1 = acc[i][j][hf * 2 + 1] + bias1[j];
                if (c < Vv && out) out[ro + c] = v0;
                if (c + 1 < Vv && out) out[ro + c + 1] = v1;
                float e0 = (c < Vv)     ? v0 : -100.f;
                float e1 = (c + 1 < Vv) ? v1 : -100.f;
                __half2 hv = __hmul2(__floats2half2_rn(e0, e1), l2e2);
                uint32_t hvu = *reinterpret_cast<uint32_t*>(&hv);
                uint32_t eo;
                asm("ex2.approx.f16x2 %0, %1;" : "=r"(eo) : "r"(hvu));
                hs = __hadd2(hs, *reinterpret_cast<__half2*>(&eo));
            }
            float rexp = __low2float(hs) + __high2float(hs);
            rexp += __shfl_xor_sync(0xffffffffu, rexp, 1);
            rexp += __shfl_xor_sync(0xffffffffu, rexp, 2);
            if ((lane & 3) == 0) atomicAdd(&g_rowsum[row], rexp);
        }
    }
}

// ======================= loss =======================
__global__ void rownll_kernel(const int* __restrict__ targets,
                              const float* __restrict__ lm_w,
                              const float* __restrict__ lmb) {
    int gw = (blockIdx.x * blockDim.x + threadIdx.x) >> 5;
    int lane = threadIdx.x & 31;
    for (int r = gw; r < BT; r += 512) {
        int tgt = targets[r];
        float dot = 0.f;
        const float* xr = &g_h[(size_t)r * Dd];
        #pragma unroll
        for (int i = 0; i < 4; i++) {
            int d = lane + 32 * i;
            dot += xr[d] * lm_w[(size_t)d * Vv + tgt];
        }
        #pragma unroll
        for (int o = 16; o; o >>= 1) dot += __shfl_xor_sync(0xffffffffu, dot, o);
        if (lane == 0) g_att[r] = logf(g_rowsum[r]) - (dot + lmb[tgt]);
    }
}

__global__ void lossred_kernel(float* __restrict__ loss_out) {
    int tid = threadIdx.x;
    float local = 0.f;
    for (int r = tid; r < BT; r += 1024) local += g_att[r];
    #pragma unroll
    for (int o = 16; o; o >>= 1) local += __shfl_xor_sync(0xffffffffu, local, o);
    __shared__ float red[32];
    if ((tid & 31) == 0) red[tid >> 5] = local;
    __syncthreads();
    if (tid < 32) {
        float v = red[tid];
        #pragma unroll
        for (int o = 16; o; o >>= 1) v += __shfl_xor_sync(0xffffffffu, v, o);
        if (tid == 0 && loss_out) *loss_out = v * (1.f / (float)BT);
    }
}

// ======================= launch =======================
extern "C" void kernel_launch(void* const* d_in, const int* in_sizes, int n_in,
                              void* d_out, int out_size) {
    const int*   idx     = (const int*)  d_in[0];
    const int*   targets = (const int*)  d_in[1];
    const float* tok_emb = (const float*)d_in[2];
    const float* pos_emb = (const float*)d_in[3];
    const float* wq      = (const float*)d_in[4];
    const float* wk      = (const float*)d_in[5];
    const float* wv      = (const float*)d_in[6];
    const float* wproj   = (const float*)d_in[7];
    const float* bproj   = (const float*)d_in[8];
    const float* w1      = (const float*)d_in[9];
    const float* b1      = (const float*)d_in[10];
    const float* w2      = (const float*)d_in[11];
    const float* b2      = (const float*)d_in[12];
    const float* ln1_g   = (const float*)d_in[13];
    const float* ln1_b   = (const float*)d_in[14];
    const float* ln2_g   = (const float*)d_in[15];
    const float* ln2_b   = (const float*)d_in[16];
    const float* lnf_g   = (const float*)d_in[17];
    const float* lnf_b   = (const float*)d_in[18];
    const float* lm_w    = (const float*)d_in[19];
    const float* lm_b    = (const float*)d_in[20];

    float* outf = (float*)d_out;
    long long btv = (long long)BT * Vv;
    float* logits = ((long long)out_size >= btv) ? outf : nullptr;
    float* lossp  = nullptr;
    if ((long long)out_size == btv + 1) lossp = outf + btv;
    else if ((long long)out_size < btv && out_size >= 1) lossp = outf + (out_size - 1);

    constexpr int LM_SMEM = (128 * LMS + 64 * LMS) * 2;  // 101376
    cudaFuncSetAttribute(lmhead_hmma, cudaFuncAttributeMaxDynamicSharedMemorySize, LM_SMEM);

    prep_kernel<<<256, 256>>>(wq, wk, wv);
    convw_kernel<<<dim3(VP / 32, 4), dim3(32, 8)>>>(lm_w);
    embed_kernel<<<BT, 128>>>(idx, tok_emb, pos_emb);

    for (int l = 0; l < Ll; l++) {
        ln_kernel<<<BT, 128>>>(ln1_g + l * Dd, ln1_b + l * Dd);
        gemm64_kernel<<<dim3(384 / 64, BT / 64), 256>>>(
            1, nullptr, l * Dd * 384, nullptr, 0, 2, 384, 128, 0);
        attn_kernel<<<Bb * Hh, 128>>>();
        gemm64_kernel<<<dim3(128 / 64, BT / 64), 256>>>(
            3, wproj + (size_t)l * Dd * Dd, 0, bproj + l * Dd, 1, 0, 128, 128, 0);
        ln_kernel<<<BT, 128>>>(ln2_g + l * Dd, ln2_b + l * Dd);
        gemm64_kernel<<<dim3(512 / 64, BT / 64), 256>>>(
            1, w1 + (size_t)l * Dd * 4 * Dd, 0, b1 + l * 4 * Dd, 0, 4, 512, 128, 1);
        gemm64_kernel<<<dim3(128 / 64, BT / 64), 256>>>(
            4, w2 + (size_t)l * 4 * Dd * Dd, 0, b2 + l * Dd, 1, 0, 128, 512, 0);
    }
    ln_kernel<<<BT, 128>>>(lnf_g, lnf_b);
    convh_kernel<<<(BT * Dd + 255) / 256, 256>>>();
    lmhead_hmma<<<dim3(BT / 128, VP / 64), 256, LM_SMEM>>>(lm_b, logits);
    rownll_kernel<<<64, 256>>>(targets, lm_w, lm_b);
    lossred_kernel<<<1, 1024>>>(lossp);
}